// round 11
// baseline (speedup 1.0000x reference)
#include <cuda_runtime.h>
#include <math.h>
#include <stdint.h>

#define GX 200
#define GY 200
#define GZ 16
#define NVOX (GX*GY*GZ)
#define NCOL (GX*GY)          // 40000 xy columns
#define F_N 8
#define G_MAX 32768
#define CAP 256               // per-column entry capacity (avg ~19, Poisson tail safe)

// scratch (static __device__ arrays: allocation-free)
__device__ int    g_count[NCOL];
__device__ int    g_entries[NCOL * CAP];
__device__ float4 g_packed[G_MAX * 5];

// ---------------- Pass 1: pack params + bin gaussians into xy-column lists ----------------
__global__ void gv_bin_kernel(const float* __restrict__ means,
                              const float* __restrict__ opac,
                              const float* __restrict__ cov,
                              const float* __restrict__ feat,
                              int G) {
    int g = blockIdx.x * blockDim.x + threadIdx.x;
    if (g >= G || g >= G_MAX) return;

    const float lox = -40.f, loy = -40.f, loz = -1.f;
    const float hix =  40.f, hiy =  40.f, hiz =  5.4f;
    const float VOX = 0.4f;

    float mx = means[g*3 + 0];
    float my = means[g*3 + 1];
    float mz = means[g*3 + 2];
    const float* C = cov + (size_t)g * 9;
    float c00 = C[0], c01 = C[1], c02 = C[2];
    float c11 = C[4], c12 = C[5], c22 = C[8];

    float sx = sqrtf(c00), sy = sqrtf(c11), sz = sqrtf(c22);
    float blx = mx - 3.f*sx, bly = my - 3.f*sy, blz = mz - 3.f*sz;
    float bhx = mx + 3.f*sx, bhy = my + 3.f*sy, bhz = mz + 3.f*sz;

    bool valid = (bhx > lox) && (bhy > loy) && (bhz > loz) &&
                 (blx < hix) && (bly < hiy) && (blz < hiz);

    // symmetric 3x3 inverse
    float i00 = c11*c22 - c12*c12;
    float i01 = c02*c12 - c01*c22;
    float i02 = c01*c12 - c02*c11;
    float i11 = c00*c22 - c02*c02;
    float i12 = c01*c02 - c00*c12;
    float i22 = c00*c11 - c01*c01;
    float det = c00*i00 + c01*i01 + c02*i02;
    float rdet = 1.f / det;
    float a00 = i00*rdet, a01 = i01*rdet, a02 = i02*rdet;
    float a11 = i11*rdet, a12 = i12*rdet, a22 = i22*rdet;

    float blxc = fminf(fmaxf(blx, lox), hix);
    float blyc = fminf(fmaxf(bly, loy), hiy);
    float blzc = fminf(fmaxf(blz, loz), hiz);
    float bhxc = fminf(fmaxf(bhx, lox), hix);
    float bhyc = fminf(fmaxf(bhy, loy), hiy);
    float bhzc = fminf(fmaxf(bhz, loz), hiz);

    int ilox = min((int)((blxc - lox) / VOX), GX - 1);
    int iloy = min((int)((blyc - loy) / VOX), GY - 1);
    int iloz = min((int)((blzc - loz) / VOX), GZ - 1);
    int ihix = min((int)((bhxc - lox) / VOX), GX - 1);
    int ihiy = min((int)((bhyc - loy) / VOX), GY - 1);
    int ihiz = min((int)((bhzc - loz) / VOX), GZ - 1);

    float op = opac[g];
    const float* f = feat + (size_t)g * F_N;

    int base = g * 5;
    g_packed[base + 0] = make_float4(mx, my, mz, op);
    g_packed[base + 1] = make_float4(a00, a01, a02, a11);
    g_packed[base + 2] = make_float4(a12, a22, __int_as_float(iloz), __int_as_float(ihiz));
    g_packed[base + 3] = make_float4(f[0], f[1], f[2], f[3]);
    g_packed[base + 4] = make_float4(f[4], f[5], f[6], f[7]);

    if (!valid) return;

    for (int ix = ilox; ix <= ihix; ix++) {
        for (int iy = iloy; iy <= ihiy; iy++) {
            int col = ix * GY + iy;
            int pos = atomicAdd(&g_count[col], 1);
            if (pos < CAP) g_entries[col * CAP + pos] = g;
        }
    }
}

// ---------------- Pass 2: gather per z-column, register accumulation, fused normalize ----------------
__global__ void gv_gather_kernel(float* __restrict__ out) {
    int tid = blockIdx.x * blockDim.x + threadIdx.x;
    int col = tid >> 4;          // 16 lanes (z) per column
    if (col >= NCOL) return;
    int z = tid & 15;

    const float lox = -40.f, loy = -40.f, loz = -1.f;
    const float VOX = 0.4f;

    int ix = col / GY;
    int iy = col - ix * GY;
    float wx = ((float)ix + 0.5f) * VOX + lox;
    float wy = ((float)iy + 0.5f) * VOX + loy;
    float wz = ((float)z  + 0.5f) * VOX + loz;

    int n = min(g_count[col], CAP);
    const int* elist = g_entries + (size_t)col * CAP;

    float dens = 0.f;
    float acc0 = 0.f, acc1 = 0.f, acc2 = 0.f, acc3 = 0.f;
    float acc4 = 0.f, acc5 = 0.f, acc6 = 0.f, acc7 = 0.f;

    for (int e = 0; e < n; e++) {
        int gid = elist[e];
        const float4* P = g_packed + gid * 5;
        float4 v0 = P[0];
        float4 v1 = P[1];
        float4 v2 = P[2];
        int zlo = __float_as_int(v2.z);
        int zhi = __float_as_int(v2.w);
        if (z < zlo || z > zhi) continue;

        float dx = wx - v0.x;
        float dy = wy - v0.y;
        float dz = wz - v0.z;
        float maha = v1.x*dx*dx + v1.w*dy*dy + v2.y*dz*dz
                   + 2.f*(v1.y*dx*dy + v1.z*dx*dz + v2.x*dy*dz);
        float ev = v0.w * __expf(-0.5f * maha);

        float4 v3 = P[3];
        float4 v4 = P[4];
        dens += ev;
        acc0 += ev * v3.x; acc1 += ev * v3.y; acc2 += ev * v3.z; acc3 += ev * v3.w;
        acc4 += ev * v4.x; acc5 += ev * v4.y; acc6 += ev * v4.z; acc7 += ev * v4.w;
    }

    int vox = col * GZ + z;
    out[vox] = dens;
    float s = 1.f / fmaxf(dens, 1e-6f);
    float4* fp = (float4*)(out + NVOX) + (size_t)vox * 2;
    fp[0] = make_float4(acc0 * s, acc1 * s, acc2 * s, acc3 * s);
    fp[1] = make_float4(acc4 * s, acc5 * s, acc6 * s, acc7 * s);
}

extern "C" void kernel_launch(void* const* d_in, const int* in_sizes, int n_in,
                              void* d_out, int out_size) {
    const float* means = (const float*)d_in[0];   // (G,3)
    const float* opac  = (const float*)d_in[1];   // (G,1)
    const float* cov   = (const float*)d_in[2];   // (G,3,3)
    const float* feat  = (const float*)d_in[3];   // (G,8)
    float* out = (float*)d_out;                   // [640000 density | 5120000 feats]

    int G = in_sizes[0] / 3;

    // zero the per-column counters (device symbol; memset node is capture-safe)
    void* cnt_ptr = nullptr;
    cudaGetSymbolAddress(&cnt_ptr, g_count);
    cudaMemsetAsync(cnt_ptr, 0, NCOL * sizeof(int));

    gv_bin_kernel<<<(G + 255) / 256, 256>>>(means, opac, cov, feat, G);

    int gthreads = NCOL * 16;   // 640,000
    gv_gather_kernel<<<(gthreads + 255) / 256, 256>>>(out);
}

// round 12
// speedup vs baseline: 1.1636x; 1.1636x over previous
#include <cuda_runtime.h>
#include <math.h>
#include <stdint.h>

#define GX 200
#define GY 200
#define GZ 16
#define NVOX (GX*GY*GZ)
#define NCOL (GX*GY)          // 40000 xy columns
#define F_N 8
#define G_MAX 32768
#define CAP 128               // per-column entries (Poisson mean ~16, max ~50)

// scratch (static __device__ arrays: allocation-free)
__device__ int    g_count[NCOL];
__device__ float4 g_entries[NCOL * CAP];   // {q0, q1, q2, pack(gid,zlo,zhi)}
__device__ float4 g_feats[G_MAX * 2];      // features repacked as 2 x float4

__device__ __forceinline__ float ex2f(float x) {
    float r; asm("ex2.approx.f32 %0, %1;" : "=f"(r) : "f"(x)); return r;
}

// ---------- Pass 1: per (gaussian, column) precompute z-quadratic, bin ----------
__global__ void gv_bin_kernel(const float* __restrict__ means,
                              const float* __restrict__ opac,
                              const float* __restrict__ cov,
                              const float* __restrict__ feat,
                              int G) {
    int g = blockIdx.x * blockDim.x + threadIdx.x;
    if (g >= G || g >= G_MAX) return;

    const float lox = -40.f, loy = -40.f, loz = -1.f;
    const float hix =  40.f, hiy =  40.f, hiz =  5.4f;
    const float VOX = 0.4f;
    const float NHL2E = -0.5f * 1.4426950408889634f;   // -0.5 * log2(e)

    float mx = means[g*3 + 0];
    float my = means[g*3 + 1];
    float mz = means[g*3 + 2];
    const float* C = cov + (size_t)g * 9;
    float c00 = C[0], c01 = C[1], c02 = C[2];
    float c11 = C[4], c12 = C[5], c22 = C[8];

    // repack features (always, cheap)
    const float* f = feat + (size_t)g * F_N;
    g_feats[g*2 + 0] = make_float4(f[0], f[1], f[2], f[3]);
    g_feats[g*2 + 1] = make_float4(f[4], f[5], f[6], f[7]);

    float sx = sqrtf(c00), sy = sqrtf(c11), sz = sqrtf(c22);
    float blx = mx - 3.f*sx, bly = my - 3.f*sy, blz = mz - 3.f*sz;
    float bhx = mx + 3.f*sx, bhy = my + 3.f*sy, bhz = mz + 3.f*sz;

    bool valid = (bhx > lox) && (bhy > loy) && (bhz > loz) &&
                 (blx < hix) && (bly < hiy) && (blz < hiz);
    if (!valid) return;

    // symmetric 3x3 inverse
    float i00 = c11*c22 - c12*c12;
    float i01 = c02*c12 - c01*c22;
    float i02 = c01*c12 - c02*c11;
    float i11 = c00*c22 - c02*c02;
    float i12 = c01*c02 - c00*c12;
    float i22 = c00*c11 - c01*c01;
    float det = c00*i00 + c01*i01 + c02*i02;
    float rdet = 1.f / det;
    float a00 = i00*rdet, a01 = i01*rdet, a02 = i02*rdet;
    float a11 = i11*rdet, a12 = i12*rdet, a22 = i22*rdet;

    float blxc = fminf(fmaxf(blx, lox), hix);
    float blyc = fminf(fmaxf(bly, loy), hiy);
    float blzc = fminf(fmaxf(blz, loz), hiz);
    float bhxc = fminf(fmaxf(bhx, lox), hix);
    float bhyc = fminf(fmaxf(bhy, loy), hiy);
    float bhzc = fminf(fmaxf(bhz, loz), hiz);

    int ilox = min((int)((blxc - lox) / VOX), GX - 1);
    int iloy = min((int)((blyc - loy) / VOX), GY - 1);
    int iloz = min((int)((blzc - loz) / VOX), GZ - 1);
    int ihix = min((int)((bhxc - lox) / VOX), GX - 1);
    int ihiy = min((int)((bhyc - loy) / VOX), GY - 1);
    int ihiz = min((int)((bhzc - loz) / VOX), GZ - 1);

    float op = opac[g];
    float l2op = log2f(fmaxf(op, 1e-37f));   // fold opacity into exponent
    if (op <= 0.f) l2op = -127.f;            // exp2(-127) == 0 exactly enough

    int zpack = (iloz << 16) | (ihiz << 20);

    for (int ix = ilox; ix <= ihix; ix++) {
        float dx = ((float)ix + 0.5f) * VOX + lox - mx;
        float tx0 = a00 * dx * dx;
        float lx  = a02 * dx;
        for (int iy = iloy; iy <= ihiy; iy++) {
            float dy = ((float)iy + 0.5f) * VOX + loy - my;
            float cxy = tx0 + a11*dy*dy + 2.f*a01*dx*dy;
            float L   = lx + a12*dy;                    // a02*dx + a12*dy
            // maha(wz) = cxy + 2L(wz - mz) + a22 (wz - mz)^2
            float q2 = a22;
            float q1 = 2.f*L - 2.f*a22*mz;
            float q0 = cxy - 2.f*L*mz + a22*mz*mz;
            // exponent base-2, opacity folded
            float e2 = NHL2E * q2;
            float e1 = NHL2E * q1;
            float e0 = NHL2E * q0 + l2op;

            int col = ix * GY + iy;
            int pos = atomicAdd(&g_count[col], 1);
            if (pos < CAP)
                g_entries[col * CAP + pos] =
                    make_float4(e0, e1, e2, __int_as_float(g | zpack));
        }
    }
}

// ---------- Pass 2: gather per voxel (16 z-lanes per column), fused normalize ----------
__global__ void gv_gather_kernel(float* __restrict__ out) {
    int tid = blockIdx.x * blockDim.x + threadIdx.x;
    int col = tid >> 4;
    if (col >= NCOL) return;
    int z = tid & 15;

    const float loz = -1.f;
    const float VOX = 0.4f;
    float wz = ((float)z + 0.5f) * VOX + loz;

    int n = min(g_count[col], CAP);
    const float4* elist = g_entries + (size_t)col * CAP;

    float dens = 0.f;
    float acc0 = 0.f, acc1 = 0.f, acc2 = 0.f, acc3 = 0.f;
    float acc4 = 0.f, acc5 = 0.f, acc6 = 0.f, acc7 = 0.f;

    for (int e = 0; e < n; e++) {
        float4 q = elist[e];                 // broadcast across 16 z-lanes
        int pk  = __float_as_int(q.w);
        int zlo = (pk >> 16) & 15;
        int zhi = (pk >> 20) & 15;
        if (z < zlo || z > zhi) continue;

        float ev = ex2f(q.x + wz * (q.y + q.z * wz));

        int gid = pk & 0xFFFF;
        float4 f0 = g_feats[gid*2 + 0];
        float4 f1 = g_feats[gid*2 + 1];
        dens += ev;
        acc0 += ev * f0.x; acc1 += ev * f0.y; acc2 += ev * f0.z; acc3 += ev * f0.w;
        acc4 += ev * f1.x; acc5 += ev * f1.y; acc6 += ev * f1.z; acc7 += ev * f1.w;
    }

    int vox = col * GZ + z;
    out[vox] = dens;
    float s = 1.f / fmaxf(dens, 1e-6f);
    float4* fp = (float4*)(out + NVOX) + (size_t)vox * 2;
    fp[0] = make_float4(acc0 * s, acc1 * s, acc2 * s, acc3 * s);
    fp[1] = make_float4(acc4 * s, acc5 * s, acc6 * s, acc7 * s);
}

extern "C" void kernel_launch(void* const* d_in, const int* in_sizes, int n_in,
                              void* d_out, int out_size) {
    const float* means = (const float*)d_in[0];   // (G,3)
    const float* opac  = (const float*)d_in[1];   // (G,1)
    const float* cov   = (const float*)d_in[2];   // (G,3,3)
    const float* feat  = (const float*)d_in[3];   // (G,8)
    float* out = (float*)d_out;                   // [640000 density | 5120000 feats]

    int G = in_sizes[0] / 3;

    void* cnt_ptr = nullptr;
    cudaGetSymbolAddress(&cnt_ptr, g_count);
    cudaMemsetAsync(cnt_ptr, 0, NCOL * sizeof(int));

    gv_bin_kernel<<<(G + 255) / 256, 256>>>(means, opac, cov, feat, G);

    int gthreads = NCOL * 16;   // 640,000
    gv_gather_kernel<<<(gthreads + 255) / 256, 256>>>(out);
}

// round 13
// speedup vs baseline: 1.4759x; 1.2683x over previous
#include <cuda_runtime.h>
#include <math.h>
#include <stdint.h>

#define GX 200
#define GY 200
#define GZ 16
#define NVOX (GX*GY*GZ)
#define NCOL (GX*GY)          // 40000 xy columns
#define F_N 8
#define G_MAX 32768
#define CAP 128               // per-column entries (mean ~16)

__device__ int    g_count[NCOL];
__device__ float4 g_entries[NCOL * CAP];   // {e0, e1, e2, pack(gid,zlo,zhi)}
__device__ float4 g_feats[G_MAX * 2];

__device__ __forceinline__ float ex2f(float x) {
    float r; asm("ex2.approx.f32 %0, %1;" : "=f"(r) : "f"(x)); return r;
}

// ---------- Pass 1: warp per gaussian; lanes stride bbox columns ----------
__global__ void gv_bin_kernel(const float* __restrict__ means,
                              const float* __restrict__ opac,
                              const float* __restrict__ cov,
                              const float* __restrict__ feat,
                              int G) {
    int g = (blockIdx.x * blockDim.x + threadIdx.x) >> 5;
    if (g >= G || g >= G_MAX) return;
    int lane = threadIdx.x & 31;

    const float lox = -40.f, loy = -40.f, loz = -1.f;
    const float hix =  40.f, hiy =  40.f, hiz =  5.4f;
    const float VOX = 0.4f;
    const float NHL2E = -0.5f * 1.4426950408889634f;   // -0.5 * log2(e)

    float mx = means[g*3 + 0];
    float my = means[g*3 + 1];
    float mz = means[g*3 + 2];
    const float* C = cov + (size_t)g * 9;
    float c00 = C[0], c01 = C[1], c02 = C[2];
    float c11 = C[4], c12 = C[5], c22 = C[8];

    // repack features (two lanes store one float4 each)
    if (lane == 0)
        g_feats[g*2 + 0] = make_float4(feat[(size_t)g*F_N+0], feat[(size_t)g*F_N+1],
                                       feat[(size_t)g*F_N+2], feat[(size_t)g*F_N+3]);
    if (lane == 1)
        g_feats[g*2 + 1] = make_float4(feat[(size_t)g*F_N+4], feat[(size_t)g*F_N+5],
                                       feat[(size_t)g*F_N+6], feat[(size_t)g*F_N+7]);

    float sx = sqrtf(c00), sy = sqrtf(c11), sz = sqrtf(c22);
    float blx = mx - 3.f*sx, bly = my - 3.f*sy, blz = mz - 3.f*sz;
    float bhx = mx + 3.f*sx, bhy = my + 3.f*sy, bhz = mz + 3.f*sz;

    bool valid = (bhx > lox) && (bhy > loy) && (bhz > loz) &&
                 (blx < hix) && (bly < hiy) && (blz < hiz);
    if (!valid) return;

    // symmetric 3x3 inverse
    float i00 = c11*c22 - c12*c12;
    float i01 = c02*c12 - c01*c22;
    float i02 = c01*c12 - c02*c11;
    float i11 = c00*c22 - c02*c02;
    float i12 = c01*c02 - c00*c12;
    float i22 = c00*c11 - c01*c01;
    float det = c00*i00 + c01*i01 + c02*i02;
    float rdet = 1.f / det;
    float a00 = i00*rdet, a01 = i01*rdet, a02 = i02*rdet;
    float a11 = i11*rdet, a12 = i12*rdet, a22 = i22*rdet;

    float blxc = fminf(fmaxf(blx, lox), hix);
    float blyc = fminf(fmaxf(bly, loy), hiy);
    float blzc = fminf(fmaxf(blz, loz), hiz);
    float bhxc = fminf(fmaxf(bhx, lox), hix);
    float bhyc = fminf(fmaxf(bhy, loy), hiy);
    float bhzc = fminf(fmaxf(bhz, loz), hiz);

    int ilox = min((int)((blxc - lox) / VOX), GX - 1);
    int iloy = min((int)((blyc - loy) / VOX), GY - 1);
    int iloz = min((int)((blzc - loz) / VOX), GZ - 1);
    int ihix = min((int)((bhxc - lox) / VOX), GX - 1);
    int ihiy = min((int)((bhyc - loy) / VOX), GY - 1);
    int ihiz = min((int)((bhzc - loz) / VOX), GZ - 1);

    int nx = ihix - ilox + 1;
    int ny = ihiy - iloy + 1;

    float op = opac[g];
    float l2op = (op > 0.f) ? log2f(op) : -127.f;

    int zpack = (iloz << 16) | (ihiz << 20);
    int ncols = nx * ny;

    for (int p = lane; p < ncols; p += 32) {
        int ox = p / ny;
        int oy = p - ox * ny;
        int ix = ilox + ox;
        int iy = iloy + oy;
        float dx = ((float)ix + 0.5f) * VOX + lox - mx;
        float dy = ((float)iy + 0.5f) * VOX + loy - my;
        float cxy = a00*dx*dx + a11*dy*dy + 2.f*a01*dx*dy;
        float L   = a02*dx + a12*dy;
        // maha(wz) = cxy + 2L(wz-mz) + a22(wz-mz)^2, as quadratic in wz:
        float q2 = a22;
        float q1 = 2.f*L - 2.f*a22*mz;
        float q0 = cxy - 2.f*L*mz + a22*mz*mz;
        float e2 = NHL2E * q2;
        float e1 = NHL2E * q1;
        float e0 = NHL2E * q0 + l2op;

        int col = ix * GY + iy;
        int pos = atomicAdd(&g_count[col], 1);
        if (pos < CAP)
            g_entries[col * CAP + pos] =
                make_float4(e0, e1, e2, __int_as_float(g | zpack));
    }
}

// ---------- Pass 2: 8 lanes per column, 2 z-voxels per thread, fused normalize ----------
__global__ void gv_gather_kernel(float* __restrict__ out) {
    int tid = blockIdx.x * blockDim.x + threadIdx.x;
    int col = tid >> 3;
    if (col >= NCOL) return;
    int zs = (tid & 7) << 1;           // z pair {zs, zs+1}

    const float loz = -1.f;
    const float VOX = 0.4f;
    float wz0 = ((float)zs + 0.5f) * VOX + loz;
    float wz1 = wz0 + VOX;

    int n = min(g_count[col], CAP);
    const float4* elist = g_entries + (size_t)col * CAP;

    float dens0 = 0.f, dens1 = 0.f;
    float p0 = 0.f, p1 = 0.f, p2 = 0.f, p3 = 0.f, p4 = 0.f, p5 = 0.f, p6 = 0.f, p7 = 0.f;
    float r0 = 0.f, r1 = 0.f, r2 = 0.f, r3 = 0.f, r4 = 0.f, r5 = 0.f, r6 = 0.f, r7 = 0.f;

    for (int e = 0; e < n; e++) {
        float4 q = elist[e];                 // broadcast across the 8-lane group
        int pk  = __float_as_int(q.w);
        int zlo = (pk >> 16) & 15;
        int zhi = (pk >> 20) & 15;
        bool in0 = (zs     >= zlo) & (zs     <= zhi);
        bool in1 = (zs + 1 >= zlo) & (zs + 1 <= zhi);
        if (!(in0 | in1)) continue;

        float ev0 = in0 ? ex2f(q.x + wz0 * (q.y + q.z * wz0)) : 0.f;
        float ev1 = in1 ? ex2f(q.x + wz1 * (q.y + q.z * wz1)) : 0.f;

        int gid = pk & 0xFFFF;
        float4 f0 = g_feats[gid*2 + 0];
        float4 f1 = g_feats[gid*2 + 1];
        dens0 += ev0; dens1 += ev1;
        p0 += ev0*f0.x; p1 += ev0*f0.y; p2 += ev0*f0.z; p3 += ev0*f0.w;
        p4 += ev0*f1.x; p5 += ev0*f1.y; p6 += ev0*f1.z; p7 += ev0*f1.w;
        r0 += ev1*f0.x; r1 += ev1*f0.y; r2 += ev1*f0.z; r3 += ev1*f0.w;
        r4 += ev1*f1.x; r5 += ev1*f1.y; r6 += ev1*f1.z; r7 += ev1*f1.w;
    }

    int vox = col * GZ + zs;
    out[vox]     = dens0;
    out[vox + 1] = dens1;
    float s0 = 1.f / fmaxf(dens0, 1e-6f);
    float s1 = 1.f / fmaxf(dens1, 1e-6f);
    float4* fp = (float4*)(out + NVOX) + (size_t)vox * 2;
    fp[0] = make_float4(p0*s0, p1*s0, p2*s0, p3*s0);
    fp[1] = make_float4(p4*s0, p5*s0, p6*s0, p7*s0);
    fp[2] = make_float4(r0*s1, r1*s1, r2*s1, r3*s1);
    fp[3] = make_float4(r4*s1, r5*s1, r6*s1, r7*s1);
}

extern "C" void kernel_launch(void* const* d_in, const int* in_sizes, int n_in,
                              void* d_out, int out_size) {
    const float* means = (const float*)d_in[0];   // (G,3)
    const float* opac  = (const float*)d_in[1];   // (G,1)
    const float* cov   = (const float*)d_in[2];   // (G,3,3)
    const float* feat  = (const float*)d_in[3];   // (G,8)
    float* out = (float*)d_out;                   // [640000 density | 5120000 feats]

    int G = in_sizes[0] / 3;

    void* cnt_ptr = nullptr;
    cudaGetSymbolAddress(&cnt_ptr, g_count);
    cudaMemsetAsync(cnt_ptr, 0, NCOL * sizeof(int));

    gv_bin_kernel<<<(G * 32 + 255) / 256, 256>>>(means, opac, cov, feat, G);

    int gthreads = NCOL * 8;   // 320,000
    gv_gather_kernel<<<(gthreads + 255) / 256, 256>>>(out);
}